// round 1
// baseline (speedup 1.0000x reference)
#include <cuda_runtime.h>
#include <math.h>

// ---------------------------------------------------------------------------
// MultiHeadAttention: B=8, S=1024, D=1024, H=16, HD=64
// Round 0: fp32 baseline. 3x QKV GEMM -> flash attention -> output GEMM.
// ---------------------------------------------------------------------------

#define B_  8
#define S_  1024
#define D_  1024
#define H_  16
#define HD_ 64
#define M_TOTAL (B_ * S_)          // 8192

// Scratch (allocation-free: static device globals). Layout [B, S, H*HD] so the
// per-head slice (s, h, :) is 64 contiguous floats.
__device__ float g_q[(size_t)M_TOTAL * D_];
__device__ float g_k[(size_t)M_TOTAL * D_];
__device__ float g_v[(size_t)M_TOTAL * D_];
__device__ float g_c[(size_t)M_TOTAL * D_];   // concat attention output [B,S,D]

// ---------------------------------------------------------------------------
// SGEMM:  C[m][n] = (sum_k A[m][k] * B[n][k] + bias[n]) * scale
// A row-major [M,K], B row-major [N,K] (torch Linear weight layout), both
// K-contiguous ("NT" gemm). 128x128 tile, BK=8, 256 threads, 8x8 microtile.
// ---------------------------------------------------------------------------
#define BM 128
#define BN 128
#define BK 8

__global__ __launch_bounds__(256)
void gemm_nt(const float* __restrict__ A, const float* __restrict__ Bm,
             const float* __restrict__ bias, float* __restrict__ C,
             int M, int N, int K, float scale)
{
    __shared__ float As[BK][BM];
    __shared__ float Bs[BK][BN];

    const int tid = threadIdx.x;
    const int bm  = blockIdx.y * BM;
    const int bn  = blockIdx.x * BN;
    const int tx  = tid & 15;        // 16 col-threads
    const int ty  = tid >> 4;        // 16 row-threads
    const int lrow = tid >> 1;       // 0..127
    const int lcol = (tid & 1) * 4;  // 0 or 4

    const float* Ap = A  + (size_t)(bm + lrow) * K + lcol;
    const float* Bp = Bm + (size_t)(bn + lrow) * K + lcol;

    float acc[8][8];
#pragma unroll
    for (int i = 0; i < 8; i++)
#pragma unroll
        for (int j = 0; j < 8; j++) acc[i][j] = 0.f;

    for (int k0 = 0; k0 < K; k0 += BK) {
        float4 a = *(const float4*)(Ap + k0);
        float4 b = *(const float4*)(Bp + k0);
        __syncthreads();  // previous iteration's readers done
        As[lcol + 0][lrow] = a.x; As[lcol + 1][lrow] = a.y;
        As[lcol + 2][lrow] = a.z; As[lcol + 3][lrow] = a.w;
        Bs[lcol + 0][lrow] = b.x; Bs[lcol + 1][lrow] = b.y;
        Bs[lcol + 2][lrow] = b.z; Bs[lcol + 3][lrow] = b.w;
        __syncthreads();

#pragma unroll
        for (int kk = 0; kk < BK; kk++) {
            float ar[8], br[8];
#pragma unroll
            for (int i = 0; i < 8; i++) ar[i] = As[kk][ty * 8 + i];
#pragma unroll
            for (int j = 0; j < 8; j++) br[j] = Bs[kk][tx * 8 + j];
#pragma unroll
            for (int i = 0; i < 8; i++)
#pragma unroll
                for (int j = 0; j < 8; j++)
                    acc[i][j] += ar[i] * br[j];
        }
    }

#pragma unroll
    for (int i = 0; i < 8; i++) {
        const int row = bm + ty * 8 + i;
#pragma unroll
        for (int j = 0; j < 8; j++) {
            const int col = bn + tx * 8 + j;
            C[(size_t)row * N + col] = (acc[i][j] + bias[col]) * scale;
        }
    }
}

// ---------------------------------------------------------------------------
// Flash attention, fp32. One block = one (b, h, 64-row q-tile).
// 256 threads: thread = (r, c) with r = tid>>2 (q row 0..63), c = tid&3
// (owns keys c*16..c*16+15 in score phase; dims c*16..c*16+15 in PV phase).
// Q is pre-scaled by 1/sqrt(HD) in its GEMM epilogue.
// ---------------------------------------------------------------------------
#define LDA 68                       // padded row stride (floats), 16B-aligned
#define ATTN_SMEM (4 * 64 * LDA * 4) // sQ, sK, sV, sP = 69632 bytes

__global__ __launch_bounds__(256)
void attn_kernel(const float* __restrict__ Q, const float* __restrict__ K,
                 const float* __restrict__ V, float* __restrict__ O)
{
    extern __shared__ float sm[];
    float* sQ = sm;
    float* sK = sm + 64 * LDA;
    float* sV = sm + 2 * 64 * LDA;
    float* sP = sm + 3 * 64 * LDA;

    const int q0  = blockIdx.x * 64;
    const int h   = blockIdx.y;
    const int b   = blockIdx.z;
    const int tid = threadIdx.x;
    const int r   = tid >> 2;
    const int c   = tid & 3;

    // element (s, j) of this (b,h): base + s*D + j
    const size_t base = (size_t)b * S_ * D_ + (size_t)h * HD_;

    // load Q tile (64 x 64)
    for (int f = tid; f < 64 * 16; f += 256) {
        const int row = f >> 4;
        const int c4  = (f & 15) << 2;
        *(float4*)&sQ[row * LDA + c4] =
            *(const float4*)(Q + base + (size_t)(q0 + row) * D_ + c4);
    }

    float m_i = -1e30f, l_i = 0.f;
    float acc[16];
#pragma unroll
    for (int i = 0; i < 16; i++) acc[i] = 0.f;

    for (int k0 = 0; k0 < S_; k0 += 64) {
        __syncthreads();  // everyone done with previous sK/sV/sP
        for (int f = tid; f < 64 * 16; f += 256) {
            const int row = f >> 4;
            const int c4  = (f & 15) << 2;
            *(float4*)&sK[row * LDA + c4] =
                *(const float4*)(K + base + (size_t)(k0 + row) * D_ + c4);
            *(float4*)&sV[row * LDA + c4] =
                *(const float4*)(V + base + (size_t)(k0 + row) * D_ + c4);
        }
        __syncthreads();

        // ---- scores: s[i] = qrow . k(c*16+i) ----
        float s[16];
#pragma unroll
        for (int i = 0; i < 16; i++) s[i] = 0.f;
#pragma unroll
        for (int d4 = 0; d4 < HD_; d4 += 4) {
            const float4 qv = *(const float4*)&sQ[r * LDA + d4];
#pragma unroll
            for (int i = 0; i < 16; i++) {
                const float4 kv = *(const float4*)&sK[(c * 16 + i) * LDA + d4];
                s[i] += qv.x * kv.x + qv.y * kv.y + qv.z * kv.z + qv.w * kv.w;
            }
        }

        // ---- online softmax update ----
        float mx = s[0];
#pragma unroll
        for (int i = 1; i < 16; i++) mx = fmaxf(mx, s[i]);
        mx = fmaxf(mx, __shfl_xor_sync(0xffffffffu, mx, 1));
        mx = fmaxf(mx, __shfl_xor_sync(0xffffffffu, mx, 2));

        const float new_m = fmaxf(m_i, mx);
        const float alpha = __expf(m_i - new_m);
        float psum = 0.f;
#pragma unroll
        for (int i = 0; i < 16; i++) {
            const float p = __expf(s[i] - new_m);
            sP[r * LDA + c * 16 + i] = p;
            psum += p;
        }
        psum += __shfl_xor_sync(0xffffffffu, psum, 1);
        psum += __shfl_xor_sync(0xffffffffu, psum, 2);
        l_i = l_i * alpha + psum;
        m_i = new_m;
#pragma unroll
        for (int i = 0; i < 16; i++) acc[i] *= alpha;

        __syncwarp();  // sP row written/read within the same quad (same warp)

        // ---- acc += P . V  (thread owns dims c*16..c*16+15 of its row) ----
#pragma unroll 16
        for (int kk = 0; kk < 64; kk++) {
            const float p  = sP[r * LDA + kk];
            const float4 v0 = *(const float4*)&sV[kk * LDA + c * 16 + 0];
            const float4 v1 = *(const float4*)&sV[kk * LDA + c * 16 + 4];
            const float4 v2 = *(const float4*)&sV[kk * LDA + c * 16 + 8];
            const float4 v3 = *(const float4*)&sV[kk * LDA + c * 16 + 12];
            acc[0]  += p * v0.x; acc[1]  += p * v0.y; acc[2]  += p * v0.z; acc[3]  += p * v0.w;
            acc[4]  += p * v1.x; acc[5]  += p * v1.y; acc[6]  += p * v1.z; acc[7]  += p * v1.w;
            acc[8]  += p * v2.x; acc[9]  += p * v2.y; acc[10] += p * v2.z; acc[11] += p * v2.w;
            acc[12] += p * v3.x; acc[13] += p * v3.y; acc[14] += p * v3.z; acc[15] += p * v3.w;
        }
    }

    const float inv = 1.f / l_i;
    const size_t ob = base + (size_t)(q0 + r) * D_ + c * 16;
    float4 o0 = make_float4(acc[0] * inv,  acc[1] * inv,  acc[2] * inv,  acc[3] * inv);
    float4 o1 = make_float4(acc[4] * inv,  acc[5] * inv,  acc[6] * inv,  acc[7] * inv);
    float4 o2 = make_float4(acc[8] * inv,  acc[9] * inv,  acc[10] * inv, acc[11] * inv);
    float4 o3 = make_float4(acc[12] * inv, acc[13] * inv, acc[14] * inv, acc[15] * inv);
    *(float4*)(O + ob + 0)  = o0;
    *(float4*)(O + ob + 4)  = o1;
    *(float4*)(O + ob + 8)  = o2;
    *(float4*)(O + ob + 12) = o3;
}

// ---------------------------------------------------------------------------
// Launch
// ---------------------------------------------------------------------------
extern "C" void kernel_launch(void* const* d_in, const int* in_sizes, int n_in,
                              void* d_out, int out_size)
{
    const float* x  = (const float*)d_in[0];
    const float* Wq = (const float*)d_in[1];
    const float* Wk = (const float*)d_in[2];
    const float* Wv = (const float*)d_in[3];
    const float* bq = (const float*)d_in[4];
    const float* bk = (const float*)d_in[5];
    const float* bv = (const float*)d_in[6];
    const float* Wo = (const float*)d_in[7];
    const float* bo = (const float*)d_in[8];
    float* out = (float*)d_out;

    float *qp, *kp, *vp, *cp;
    cudaGetSymbolAddress((void**)&qp, g_q);
    cudaGetSymbolAddress((void**)&kp, g_k);
    cudaGetSymbolAddress((void**)&vp, g_v);
    cudaGetSymbolAddress((void**)&cp, g_c);

    const dim3 ggrid(D_ / BN, M_TOTAL / BM);  // (8, 64)
    const float qscale = 0.125f;              // 1/sqrt(64), folded into Q

    // Wq/Wk/Wv [H,HD,D] flatten exactly to [1024,1024] with out-row h*64+j,
    // so q lands in [B,S,H,HD] layout directly.
    gemm_nt<<<ggrid, 256>>>(x, Wq, bq, qp, M_TOTAL, D_, D_, qscale);
    gemm_nt<<<ggrid, 256>>>(x, Wk, bk, kp, M_TOTAL, D_, D_, 1.0f);
    gemm_nt<<<ggrid, 256>>>(x, Wv, bv, vp, M_TOTAL, D_, D_, 1.0f);

    cudaFuncSetAttribute(attn_kernel,
                         cudaFuncAttributeMaxDynamicSharedMemorySize, ATTN_SMEM);
    attn_kernel<<<dim3(S_ / 64, H_, B_), 256, ATTN_SMEM>>>(qp, kp, vp, cp);

    gemm_nt<<<ggrid, 256>>>(cp, Wo, bo, out, M_TOTAL, D_, D_, 1.0f);
}

// round 2
// speedup vs baseline: 6.0432x; 6.0432x over previous
#include <cuda_runtime.h>
#include <math.h>

// ---------------------------------------------------------------------------
// MultiHeadAttention: B=8, S=1024, D=1024, H=16, HD=64
// Round 1: tf32 mma.sync everywhere. QKV GEMMs -> flash attention (tensor
// core S and PV) -> output GEMM.
// ---------------------------------------------------------------------------

#define B_  8
#define S_  1024
#define D_  1024
#define H_  16
#define HD_ 64
#define M_TOTAL (B_ * S_)          // 8192

__device__ float g_q[(size_t)M_TOTAL * D_];
__device__ float g_k[(size_t)M_TOTAL * D_];
__device__ float g_v[(size_t)M_TOTAL * D_];
__device__ float g_c[(size_t)M_TOTAL * D_];

// ---------------------------------------------------------------------------
// helpers
// ---------------------------------------------------------------------------
__device__ __forceinline__ unsigned f2tf32(float f) {
    unsigned u;
    asm("cvt.rna.tf32.f32 %0, %1;" : "=r"(u) : "f"(f));
    return u;
}

__device__ __forceinline__ void mma_tf32(float* c,
                                         unsigned a0, unsigned a1, unsigned a2, unsigned a3,
                                         unsigned b0, unsigned b1) {
    asm volatile(
        "mma.sync.aligned.m16n8k8.row.col.f32.tf32.tf32.f32 "
        "{%0,%1,%2,%3}, {%4,%5,%6,%7}, {%8,%9}, {%0,%1,%2,%3};\n"
        : "+f"(c[0]), "+f"(c[1]), "+f"(c[2]), "+f"(c[3])
        : "r"(a0), "r"(a1), "r"(a2), "r"(a3), "r"(b0), "r"(b1));
}

// k-permutation within an 8-chunk so fragment pairs (k, k+4) are adjacent:
// store order [0,4,1,5,2,6,3,7]
__device__ __forceinline__ int p8(int k) { return ((k & 3) << 1) | (k >> 2); }

// ---------------------------------------------------------------------------
// tf32 GEMM:  C[m][n] = (sum_k A[m][k] * B[n][k] + bias[n]) * scale
// A [M,K] row-major, B [N,K] row-major. 128x128x16 tile, 4 warps (64x64 each).
// ---------------------------------------------------------------------------
#define GBM 128
#define GBN 128
#define GBK 16
#define GLD 18   // padded row stride (floats)

__global__ __launch_bounds__(128)
void gemm_tc(const float* __restrict__ A, const float* __restrict__ Bm,
             const float* __restrict__ bias, float* __restrict__ C,
             int M, int N, int K, float scale)
{
    __shared__ float As[GBM * GLD];
    __shared__ float Bs[GBN * GLD];

    const int tid  = threadIdx.x;
    const int wid  = tid >> 5;
    const int lane = tid & 31;
    const int g    = lane >> 2;      // group id 0..7
    const int tig  = lane & 3;       // thread-in-group 0..3
    const int wm   = (wid & 1) * 64;
    const int wn   = (wid >> 1) * 64;
    const int bm   = blockIdx.y * GBM;
    const int bn   = blockIdx.x * GBN;

    // staging thread map: row r, 4 float4-cols per row
    const int r  = tid >> 2;         // 0..31 (4 passes of 32 rows)
    const int c4 = (tid & 3) * 4;    // 0,4,8,12
    const int sbase = ((c4 >> 3) << 3) + ((c4 & 4) ? 1 : 0);  // permuted store base

    float acc[4][8][4];
#pragma unroll
    for (int mt = 0; mt < 4; mt++)
#pragma unroll
        for (int nt = 0; nt < 8; nt++)
#pragma unroll
            for (int i = 0; i < 4; i++) acc[mt][nt][i] = 0.f;

    for (int k0 = 0; k0 < K; k0 += GBK) {
        float4 av[4], bv[4];
#pragma unroll
        for (int p = 0; p < 4; p++) {
            av[p] = *(const float4*)(A  + (size_t)(bm + r + 32 * p) * K + k0 + c4);
            bv[p] = *(const float4*)(Bm + (size_t)(bn + r + 32 * p) * K + k0 + c4);
        }
        __syncthreads();
#pragma unroll
        for (int p = 0; p < 4; p++) {
            float* ar = &As[(r + 32 * p) * GLD + sbase];
            float* br = &Bs[(r + 32 * p) * GLD + sbase];
            ar[0] = __uint_as_float(f2tf32(av[p].x));
            ar[2] = __uint_as_float(f2tf32(av[p].y));
            ar[4] = __uint_as_float(f2tf32(av[p].z));
            ar[6] = __uint_as_float(f2tf32(av[p].w));
            br[0] = __uint_as_float(f2tf32(bv[p].x));
            br[2] = __uint_as_float(f2tf32(bv[p].y));
            br[4] = __uint_as_float(f2tf32(bv[p].z));
            br[6] = __uint_as_float(f2tf32(bv[p].w));
        }
        __syncthreads();

#pragma unroll
        for (int ks = 0; ks < 2; ks++) {
            unsigned af[4][4];
#pragma unroll
            for (int mt = 0; mt < 4; mt++) {
                float2 lo = *(float2*)&As[(wm + mt * 16 + g)     * GLD + ks * 8 + 2 * tig];
                float2 hi = *(float2*)&As[(wm + mt * 16 + g + 8) * GLD + ks * 8 + 2 * tig];
                af[mt][0] = __float_as_uint(lo.x);
                af[mt][1] = __float_as_uint(hi.x);
                af[mt][2] = __float_as_uint(lo.y);
                af[mt][3] = __float_as_uint(hi.y);
            }
            unsigned bf[8][2];
#pragma unroll
            for (int nt = 0; nt < 8; nt++) {
                float2 b = *(float2*)&Bs[(wn + nt * 8 + g) * GLD + ks * 8 + 2 * tig];
                bf[nt][0] = __float_as_uint(b.x);
                bf[nt][1] = __float_as_uint(b.y);
            }
#pragma unroll
            for (int mt = 0; mt < 4; mt++)
#pragma unroll
                for (int nt = 0; nt < 8; nt++)
                    mma_tf32(acc[mt][nt], af[mt][0], af[mt][1], af[mt][2], af[mt][3],
                             bf[nt][0], bf[nt][1]);
        }
    }

    // epilogue
#pragma unroll
    for (int mt = 0; mt < 4; mt++) {
        const int row0 = bm + wm + mt * 16 + g;
#pragma unroll
        for (int nt = 0; nt < 8; nt++) {
            const int col = bn + wn + nt * 8 + 2 * tig;
            const float b0 = bias[col], b1 = bias[col + 1];
            float2 v0 = make_float2((acc[mt][nt][0] + b0) * scale,
                                    (acc[mt][nt][1] + b1) * scale);
            float2 v1 = make_float2((acc[mt][nt][2] + b0) * scale,
                                    (acc[mt][nt][3] + b1) * scale);
            *(float2*)(C + (size_t)row0 * N + col)       = v0;
            *(float2*)(C + (size_t)(row0 + 8) * N + col) = v1;
        }
    }
}

// ---------------------------------------------------------------------------
// Flash attention with tf32 mma. Block = (b, h, 64-row q-tile), 4 warps.
// Warp w owns q rows [w*16, w*16+16). smem tiles are k-permuted for LDS.64
// fragment loads; V is stored transposed [d][key] for PV B-fragments.
// ---------------------------------------------------------------------------
#define ALD 70                                  // padded row stride
#define ATTN_SMEM (4 * 64 * ALD * 4)            // sQ, sK, sVt, sP

__global__ __launch_bounds__(128)
void attn_tc(const float* __restrict__ Q, const float* __restrict__ K,
             const float* __restrict__ V, float* __restrict__ O)
{
    extern __shared__ float sm[];
    float* sQ  = sm;
    float* sK  = sm + 64 * ALD;
    float* sVt = sm + 2 * 64 * ALD;
    float* sP  = sm + 3 * 64 * ALD;

    const int q0   = blockIdx.x * 64;
    const int h    = blockIdx.y;
    const int b    = blockIdx.z;
    const int tid  = threadIdx.x;
    const int w    = tid >> 5;
    const int lane = tid & 31;
    const int g    = lane >> 2;
    const int tig  = lane & 3;

    const size_t base = (size_t)b * S_ * D_ + (size_t)h * HD_;

    // load Q tile (64x64) with k-permutation + tf32 convert
    for (int f = tid; f < 64 * 16; f += 128) {
        const int row = f >> 4;
        const int c4  = (f & 15) << 2;                     // 0..60
        const float4 qv = *(const float4*)(Q + base + (size_t)(q0 + row) * D_ + c4);
        const int sb = ((c4 >> 3) << 3) + ((c4 & 4) ? 1 : 0);
        float* dst = &sQ[row * ALD + sb];
        dst[0] = __uint_as_float(f2tf32(qv.x));
        dst[2] = __uint_as_float(f2tf32(qv.y));
        dst[4] = __uint_as_float(f2tf32(qv.z));
        dst[6] = __uint_as_float(f2tf32(qv.w));
    }

    float m0 = -1e30f, m1 = -1e30f, l0 = 0.f, l1 = 0.f;
    float o[8][4];
#pragma unroll
    for (int nt = 0; nt < 8; nt++)
#pragma unroll
        for (int i = 0; i < 4; i++) o[nt][i] = 0.f;

    const int pc0 = p8(2 * tig);       // permuted col for S col 2*tig
    const int pc1 = p8(2 * tig + 1);   // permuted col for S col 2*tig+1

    for (int k0 = 0; k0 < S_; k0 += 64) {
        __syncthreads();   // previous tile fully consumed (also publishes sQ on iter 0)
        for (int f = tid; f < 64 * 16; f += 128) {
            const int row = f >> 4;                        // key
            const int c4  = (f & 15) << 2;                 // d base
            const float4 kv = *(const float4*)(K + base + (size_t)(k0 + row) * D_ + c4);
            const float4 vv = *(const float4*)(V + base + (size_t)(k0 + row) * D_ + c4);
            const int sb = ((c4 >> 3) << 3) + ((c4 & 4) ? 1 : 0);
            float* dk = &sK[row * ALD + sb];
            dk[0] = __uint_as_float(f2tf32(kv.x));
            dk[2] = __uint_as_float(f2tf32(kv.y));
            dk[4] = __uint_as_float(f2tf32(kv.z));
            dk[6] = __uint_as_float(f2tf32(kv.w));
            const int kp = ((row >> 3) << 3) + p8(row & 7);  // permuted key pos
            sVt[(c4 + 0) * ALD + kp] = __uint_as_float(f2tf32(vv.x));
            sVt[(c4 + 1) * ALD + kp] = __uint_as_float(f2tf32(vv.y));
            sVt[(c4 + 2) * ALD + kp] = __uint_as_float(f2tf32(vv.z));
            sVt[(c4 + 3) * ALD + kp] = __uint_as_float(f2tf32(vv.w));
        }
        __syncthreads();

        // ---- S = Q . K^T  (warp: 16 q-rows x 64 keys) ----
        float s[8][4];
#pragma unroll
        for (int nt = 0; nt < 8; nt++)
#pragma unroll
            for (int i = 0; i < 4; i++) s[nt][i] = 0.f;

#pragma unroll
        for (int ks = 0; ks < 8; ks++) {
            float2 lo = *(float2*)&sQ[(w * 16 + g)     * ALD + ks * 8 + 2 * tig];
            float2 hi = *(float2*)&sQ[(w * 16 + g + 8) * ALD + ks * 8 + 2 * tig];
            unsigned a0 = __float_as_uint(lo.x), a1 = __float_as_uint(hi.x);
            unsigned a2 = __float_as_uint(lo.y), a3 = __float_as_uint(hi.y);
#pragma unroll
            for (int nt = 0; nt < 8; nt++) {
                float2 bb = *(float2*)&sK[(nt * 8 + g) * ALD + ks * 8 + 2 * tig];
                mma_tf32(s[nt], a0, a1, a2, a3,
                         __float_as_uint(bb.x), __float_as_uint(bb.y));
            }
        }

        // ---- online softmax (rows g and g+8 of this warp's 16) ----
        float mx0 = -1e30f, mx1 = -1e30f;
#pragma unroll
        for (int nt = 0; nt < 8; nt++) {
            mx0 = fmaxf(mx0, fmaxf(s[nt][0], s[nt][1]));
            mx1 = fmaxf(mx1, fmaxf(s[nt][2], s[nt][3]));
        }
        mx0 = fmaxf(mx0, __shfl_xor_sync(0xffffffffu, mx0, 1));
        mx0 = fmaxf(mx0, __shfl_xor_sync(0xffffffffu, mx0, 2));
        mx1 = fmaxf(mx1, __shfl_xor_sync(0xffffffffu, mx1, 1));
        mx1 = fmaxf(mx1, __shfl_xor_sync(0xffffffffu, mx1, 2));

        const float nm0 = fmaxf(m0, mx0);
        const float nm1 = fmaxf(m1, mx1);
        const float al0 = __expf(m0 - nm0);
        const float al1 = __expf(m1 - nm1);
        m0 = nm0; m1 = nm1;

        const int row0 = w * 16 + g;
        float ps0 = 0.f, ps1 = 0.f;
#pragma unroll
        for (int nt = 0; nt < 8; nt++) {
            const float p0 = __expf(s[nt][0] - nm0);
            const float p1 = __expf(s[nt][1] - nm0);
            const float p2 = __expf(s[nt][2] - nm1);
            const float p3 = __expf(s[nt][3] - nm1);
            ps0 += p0 + p1;
            ps1 += p2 + p3;
            sP[row0 * ALD + nt * 8 + pc0]       = __uint_as_float(f2tf32(p0));
            sP[row0 * ALD + nt * 8 + pc1]       = __uint_as_float(f2tf32(p1));
            sP[(row0 + 8) * ALD + nt * 8 + pc0] = __uint_as_float(f2tf32(p2));
            sP[(row0 + 8) * ALD + nt * 8 + pc1] = __uint_as_float(f2tf32(p3));
        }
        ps0 += __shfl_xor_sync(0xffffffffu, ps0, 1);
        ps0 += __shfl_xor_sync(0xffffffffu, ps0, 2);
        ps1 += __shfl_xor_sync(0xffffffffu, ps1, 1);
        ps1 += __shfl_xor_sync(0xffffffffu, ps1, 2);
        l0 = l0 * al0 + ps0;
        l1 = l1 * al1 + ps1;

#pragma unroll
        for (int nt = 0; nt < 8; nt++) {
            o[nt][0] *= al0; o[nt][1] *= al0;
            o[nt][2] *= al1; o[nt][3] *= al1;
        }

        __syncwarp();   // sP rows are private to this warp

        // ---- O += P . V ----
#pragma unroll
        for (int ks = 0; ks < 8; ks++) {
            float2 lo = *(float2*)&sP[(w * 16 + g)     * ALD + ks * 8 + 2 * tig];
            float2 hi = *(float2*)&sP[(w * 16 + g + 8) * ALD + ks * 8 + 2 * tig];
            unsigned a0 = __float_as_uint(lo.x), a1 = __float_as_uint(hi.x);
            unsigned a2 = __float_as_uint(lo.y), a3 = __float_as_uint(hi.y);
#pragma unroll
            for (int nt = 0; nt < 8; nt++) {
                float2 bb = *(float2*)&sVt[(nt * 8 + g) * ALD + ks * 8 + 2 * tig];
                mma_tf32(o[nt], a0, a1, a2, a3,
                         __float_as_uint(bb.x), __float_as_uint(bb.y));
            }
        }
    }

    // ---- write out: O[q][d] / l ----
    const float inv0 = 1.f / l0;
    const float inv1 = 1.f / l1;
    const int row = q0 + w * 16 + g;
#pragma unroll
    for (int nt = 0; nt < 8; nt++) {
        const int col = nt * 8 + 2 * tig;   // within head dim... spans 64
        float2 v0 = make_float2(o[nt][0] * inv0, o[nt][1] * inv0);
        float2 v1 = make_float2(o[nt][2] * inv1, o[nt][3] * inv1);
        *(float2*)(O + base + (size_t)row * D_ + col)       = v0;
        *(float2*)(O + base + (size_t)(row + 8) * D_ + col) = v1;
    }
}

// ---------------------------------------------------------------------------
// Launch
// ---------------------------------------------------------------------------
extern "C" void kernel_launch(void* const* d_in, const int* in_sizes, int n_in,
                              void* d_out, int out_size)
{
    const float* x  = (const float*)d_in[0];
    const float* Wq = (const float*)d_in[1];
    const float* Wk = (const float*)d_in[2];
    const float* Wv = (const float*)d_in[3];
    const float* bq = (const float*)d_in[4];
    const float* bk = (const float*)d_in[5];
    const float* bv = (const float*)d_in[6];
    const float* Wo = (const float*)d_in[7];
    const float* bo = (const float*)d_in[8];
    float* out = (float*)d_out;

    float *qp, *kp, *vp, *cp;
    cudaGetSymbolAddress((void**)&qp, g_q);
    cudaGetSymbolAddress((void**)&kp, g_k);
    cudaGetSymbolAddress((void**)&vp, g_v);
    cudaGetSymbolAddress((void**)&cp, g_c);

    const dim3 ggrid(D_ / GBN, M_TOTAL / GBM);  // (8, 64)
    const float qscale = 0.125f;                // 1/sqrt(64) folded into Q

    gemm_tc<<<ggrid, 128>>>(x, Wq, bq, qp, M_TOTAL, D_, D_, qscale);
    gemm_tc<<<ggrid, 128>>>(x, Wk, bk, kp, M_TOTAL, D_, D_, 1.0f);
    gemm_tc<<<ggrid, 128>>>(x, Wv, bv, vp, M_TOTAL, D_, D_, 1.0f);

    cudaFuncSetAttribute(attn_tc,
                         cudaFuncAttributeMaxDynamicSharedMemorySize, ATTN_SMEM);
    attn_tc<<<dim3(S_ / 64, H_, B_), 128, ATTN_SMEM>>>(qp, kp, vp, cp);

    gemm_tc<<<ggrid, 128>>>(cp, Wo, bo, out, M_TOTAL, D_, D_, 1.0f);
}

// round 4
// speedup vs baseline: 7.2486x; 1.1995x over previous
#include <cuda_runtime.h>
#include <cstdint>
#include <math.h>

// ---------------------------------------------------------------------------
// MultiHeadAttention: B=8, S=1024, D=1024, H=16, HD=64
// Round 3: all-mma.sync tf32 (tcgen05 unavailable: harness targets compute_103
// PTX without the 'a' feature set). Pipelined GEMMs + low-smem-traffic
// flash attention (128 q-rows/CTA, register-resident P, no V transpose).
// ---------------------------------------------------------------------------

#define B_  8
#define S_  1024
#define D_  1024
#define H_  16
#define HD_ 64
#define M_TOTAL (B_ * S_)          // 8192

__device__ float g_q[(size_t)M_TOTAL * D_];
__device__ float g_k[(size_t)M_TOTAL * D_];
__device__ float g_v[(size_t)M_TOTAL * D_];
__device__ float g_c[(size_t)M_TOTAL * D_];

// ---------------------------------------------------------------------------
// helpers
// ---------------------------------------------------------------------------
__device__ __forceinline__ unsigned f2tf32(float f) {
    unsigned u;
    asm("cvt.rna.tf32.f32 %0, %1;" : "=r"(u) : "f"(f));
    return u;
}

__device__ __forceinline__ void mma_tf32(float* c,
                                         unsigned a0, unsigned a1, unsigned a2, unsigned a3,
                                         unsigned b0, unsigned b1) {
    asm volatile(
        "mma.sync.aligned.m16n8k8.row.col.f32.tf32.tf32.f32 "
        "{%0,%1,%2,%3}, {%4,%5,%6,%7}, {%8,%9}, {%0,%1,%2,%3};\n"
        : "+f"(c[0]), "+f"(c[1]), "+f"(c[2]), "+f"(c[3])
        : "r"(a0), "r"(a1), "r"(a2), "r"(a3), "r"(b0), "r"(b1));
}

// ---------------------------------------------------------------------------
// tf32 GEMM: C[m][n] = (sum_k A[m][k]*B[n][k] + bias[n]) * scale
// 128x128 CTA tile, 8 warps (32x64 warp tile), BK=16, double-buffered smem,
// LDG prefetch 2 slabs ahead. k-permuted pairs (k,k+4) adjacent for LDS.64.
// GLD=24 => fragment LDS.64 is bank-conflict-free per 16-lane phase.
// ---------------------------------------------------------------------------
#define GBM 128
#define GBN 128
#define GBK 16
#define GLD 24

__global__ __launch_bounds__(256)
void gemm_tc(const float* __restrict__ A, const float* __restrict__ Bm,
             const float* __restrict__ bias, float* __restrict__ C,
             int M, int N, int K, float scale)
{
    __shared__ float As[2][GBM * GLD];
    __shared__ float Bs[2][GBN * GLD];

    const int tid  = threadIdx.x;
    const int wid  = tid >> 5;
    const int lane = tid & 31;
    const int g    = lane >> 2;
    const int tig  = lane & 3;
    const int wm   = (wid & 3) * 32;
    const int wn   = (wid >> 2) * 64;
    const int bm   = blockIdx.y * GBM;
    const int bn   = blockIdx.x * GBN;

    const int r  = tid >> 2;                    // 0..63
    const int c4 = (tid & 3) * 4;               // 0,4,8,12
    const int sb = ((c4 >> 3) << 3) + ((c4 & 4) ? 1 : 0);   // permuted store base

    const float* Ar0 = A  + (size_t)(bm + r) * K + c4;
    const float* Ar1 = A  + (size_t)(bm + r + 64) * K + c4;
    const float* Br0 = Bm + (size_t)(bn + r) * K + c4;
    const float* Br1 = Bm + (size_t)(bn + r + 64) * K + c4;

    float4 pa0, pa1, pb0, pb1;

#define LDG_SLAB(t) do {                                  \
        pa0 = *(const float4*)(Ar0 + (size_t)(t) * GBK);  \
        pa1 = *(const float4*)(Ar1 + (size_t)(t) * GBK);  \
        pb0 = *(const float4*)(Br0 + (size_t)(t) * GBK);  \
        pb1 = *(const float4*)(Br1 + (size_t)(t) * GBK);  \
    } while (0)

#define STS_ONE(dst, v) do {                              \
        (dst)[0] = __uint_as_float(f2tf32((v).x));        \
        (dst)[2] = __uint_as_float(f2tf32((v).y));        \
        (dst)[4] = __uint_as_float(f2tf32((v).z));        \
        (dst)[6] = __uint_as_float(f2tf32((v).w));        \
    } while (0)

#define STS_SLAB(bf) do {                                 \
        STS_ONE(&As[bf][r * GLD + sb],        pa0);       \
        STS_ONE(&As[bf][(r + 64) * GLD + sb], pa1);       \
        STS_ONE(&Bs[bf][r * GLD + sb],        pb0);       \
        STS_ONE(&Bs[bf][(r + 64) * GLD + sb], pb1);       \
    } while (0)

    float acc[2][8][4];
#pragma unroll
    for (int mt = 0; mt < 2; mt++)
#pragma unroll
        for (int nt = 0; nt < 8; nt++)
#pragma unroll
            for (int i = 0; i < 4; i++) acc[mt][nt][i] = 0.f;

    const int NT = K / GBK;    // 64
    LDG_SLAB(0);
    STS_SLAB(0);
    LDG_SLAB(1);
    __syncthreads();

    for (int t = 0; t < NT; t++) {
        if (t + 1 < NT) STS_SLAB((t + 1) & 1);   // regs hold slab t+1
        if (t + 2 < NT) LDG_SLAB(t + 2);

        const float* as = As[t & 1];
        const float* bs = Bs[t & 1];
#pragma unroll
        for (int ks = 0; ks < 2; ks++) {
            unsigned af[2][4];
#pragma unroll
            for (int mt = 0; mt < 2; mt++) {
                float2 lo = *(const float2*)&as[(wm + mt * 16 + g)     * GLD + ks * 8 + 2 * tig];
                float2 hi = *(const float2*)&as[(wm + mt * 16 + g + 8) * GLD + ks * 8 + 2 * tig];
                af[mt][0] = __float_as_uint(lo.x);
                af[mt][1] = __float_as_uint(hi.x);
                af[mt][2] = __float_as_uint(lo.y);
                af[mt][3] = __float_as_uint(hi.y);
            }
            unsigned bfr[8][2];
#pragma unroll
            for (int nt = 0; nt < 8; nt++) {
                float2 b = *(const float2*)&bs[(wn + nt * 8 + g) * GLD + ks * 8 + 2 * tig];
                bfr[nt][0] = __float_as_uint(b.x);
                bfr[nt][1] = __float_as_uint(b.y);
            }
#pragma unroll
            for (int mt = 0; mt < 2; mt++)
#pragma unroll
                for (int nt = 0; nt < 8; nt++)
                    mma_tf32(acc[mt][nt], af[mt][0], af[mt][1], af[mt][2], af[mt][3],
                             bfr[nt][0], bfr[nt][1]);
        }
        __syncthreads();
    }

#pragma unroll
    for (int mt = 0; mt < 2; mt++) {
        const int row0 = bm + wm + mt * 16 + g;
#pragma unroll
        for (int nt = 0; nt < 8; nt++) {
            const int col = bn + wn + nt * 8 + 2 * tig;
            const float b0 = bias[col], b1 = bias[col + 1];
            float2 v0 = make_float2((acc[mt][nt][0] + b0) * scale,
                                    (acc[mt][nt][1] + b1) * scale);
            float2 v1 = make_float2((acc[mt][nt][2] + b0) * scale,
                                    (acc[mt][nt][3] + b1) * scale);
            *(float2*)(C + (size_t)row0 * N + col)       = v0;
            *(float2*)(C + (size_t)(row0 + 8) * N + col) = v1;
        }
    }
#undef LDG_SLAB
#undef STS_ONE
#undef STS_SLAB
}

// ---------------------------------------------------------------------------
// Flash attention, tf32 mma.sync.
// CTA = (b, h, 128-row q-tile), 4 warps, each warp owns 32 q rows (2 m-tiles).
// Plain (non-permuted) smem layouts, conflict-free pads:
//   sQ [128][68], sK [64][68]  -> frag LDS.32 banks (4g+tig) distinct
//   sV [64][72]                -> PV B-frag LDS.32 banks (8*tig+g) distinct
// P stays in registers: S C-fragment -> PV A-fragment via quad shuffles.
// ---------------------------------------------------------------------------
#define QLD 68
#define KLD 68
#define VLD 72
#define ATTN_SMEM ((128 * QLD + 64 * KLD + 64 * VLD) * 4)   // 70656 B

__device__ __forceinline__ void p2afrag(const float sv[4], int lane, int tig,
                                        unsigned& a0, unsigned& a1,
                                        unsigned& a2, unsigned& a3) {
    const unsigned F = 0xffffffffu;
    const int s0l = (lane & ~3) | (tig >> 1);
    const int s1l = s0l + 2;
    float v00 = __shfl_sync(F, sv[0], s0l);
    float v01 = __shfl_sync(F, sv[1], s0l);
    float v10 = __shfl_sync(F, sv[0], s1l);
    float v11 = __shfl_sync(F, sv[1], s1l);
    float w00 = __shfl_sync(F, sv[2], s0l);
    float w01 = __shfl_sync(F, sv[3], s0l);
    float w10 = __shfl_sync(F, sv[2], s1l);
    float w11 = __shfl_sync(F, sv[3], s1l);
    const bool odd = (tig & 1);
    a0 = f2tf32(odd ? v01 : v00);
    a2 = f2tf32(odd ? v11 : v10);
    a1 = f2tf32(odd ? w01 : w00);
    a3 = f2tf32(odd ? w11 : w10);
}

__global__ __launch_bounds__(128)
void attn_tc(const float* __restrict__ Q, const float* __restrict__ K,
             const float* __restrict__ V, float* __restrict__ O)
{
    extern __shared__ float sm[];
    float* sQ = sm;                          // [128][QLD]
    float* sK = sm + 128 * QLD;              // [64][KLD]
    float* sV = sm + 128 * QLD + 64 * KLD;   // [64][VLD]

    const int q0   = blockIdx.x * 128;
    const int h    = blockIdx.y;
    const int b    = blockIdx.z;
    const int tid  = threadIdx.x;
    const int w    = tid >> 5;
    const int lane = tid & 31;
    const int g    = lane >> 2;
    const int tig  = lane & 3;

    const size_t base = (size_t)b * S_ * D_ + (size_t)h * HD_;

    // ---- load Q tile (128 x 64), plain layout, tf32-converted ----
    for (int f = tid; f < 128 * 16; f += 128) {
        const int row = f >> 4;
        const int c4  = (f & 15) << 2;
        const float4 qv = *(const float4*)(Q + base + (size_t)(q0 + row) * D_ + c4);
        float4 qt;
        qt.x = __uint_as_float(f2tf32(qv.x));
        qt.y = __uint_as_float(f2tf32(qv.y));
        qt.z = __uint_as_float(f2tf32(qv.z));
        qt.w = __uint_as_float(f2tf32(qv.w));
        *(float4*)&sQ[row * QLD + c4] = qt;
    }

    float mrow[2][2], lrow[2][2];
#pragma unroll
    for (int mt = 0; mt < 2; mt++) {
        mrow[mt][0] = -1e30f; mrow[mt][1] = -1e30f;
        lrow[mt][0] = 0.f;    lrow[mt][1] = 0.f;
    }
    float o[2][8][4];
#pragma unroll
    for (int mt = 0; mt < 2; mt++)
#pragma unroll
        for (int nt = 0; nt < 8; nt++)
#pragma unroll
            for (int i = 0; i < 4; i++) o[mt][nt][i] = 0.f;

    for (int k0 = 0; k0 < S_; k0 += 64) {
        __syncthreads();   // previous tile consumed (publishes sQ on iter 0)
        for (int f = tid; f < 64 * 16; f += 128) {
            const int row = f >> 4;
            const int c4  = (f & 15) << 2;
            const float4 kv = *(const float4*)(K + base + (size_t)(k0 + row) * D_ + c4);
            const float4 vv = *(const float4*)(V + base + (size_t)(k0 + row) * D_ + c4);
            float4 kt, vt;
            kt.x = __uint_as_float(f2tf32(kv.x)); kt.y = __uint_as_float(f2tf32(kv.y));
            kt.z = __uint_as_float(f2tf32(kv.z)); kt.w = __uint_as_float(f2tf32(kv.w));
            vt.x = __uint_as_float(f2tf32(vv.x)); vt.y = __uint_as_float(f2tf32(vv.y));
            vt.z = __uint_as_float(f2tf32(vv.z)); vt.w = __uint_as_float(f2tf32(vv.w));
            *(float4*)&sK[row * KLD + c4] = kt;
            *(float4*)&sV[row * VLD + c4] = vt;
        }
        __syncthreads();

        // ---- S = Q . K^T : 2 m-tiles x 64 keys per warp ----
        float s[2][8][4];
#pragma unroll
        for (int mt = 0; mt < 2; mt++)
#pragma unroll
            for (int nt = 0; nt < 8; nt++)
#pragma unroll
                for (int i = 0; i < 4; i++) s[mt][nt][i] = 0.f;

#pragma unroll
        for (int ks = 0; ks < 8; ks++) {
            unsigned af[2][4];
#pragma unroll
            for (int mt = 0; mt < 2; mt++) {
                const int qr = (w * 32 + mt * 16 + g) * QLD + ks * 8;
                af[mt][0] = __float_as_uint(sQ[qr + tig]);
                af[mt][1] = __float_as_uint(sQ[qr + 8 * QLD + tig]);
                af[mt][2] = __float_as_uint(sQ[qr + tig + 4]);
                af[mt][3] = __float_as_uint(sQ[qr + 8 * QLD + tig + 4]);
            }
#pragma unroll
            for (int nt = 0; nt < 8; nt++) {
                const int kr = (nt * 8 + g) * KLD + ks * 8;
                const unsigned b0 = __float_as_uint(sK[kr + tig]);
                const unsigned b1 = __float_as_uint(sK[kr + tig + 4]);
                mma_tf32(s[0][nt], af[0][0], af[0][1], af[0][2], af[0][3], b0, b1);
                mma_tf32(s[1][nt], af[1][0], af[1][1], af[1][2], af[1][3], b0, b1);
            }
        }

        // ---- online softmax per m-tile; s becomes P (fp32) in place ----
#pragma unroll
        for (int mt = 0; mt < 2; mt++) {
            float mx0 = -1e30f, mx1 = -1e30f;
#pragma unroll
            for (int nt = 0; nt < 8; nt++) {
                mx0 = fmaxf(mx0, fmaxf(s[mt][nt][0], s[mt][nt][1]));
                mx1 = fmaxf(mx1, fmaxf(s[mt][nt][2], s[mt][nt][3]));
            }
            mx0 = fmaxf(mx0, __shfl_xor_sync(0xffffffffu, mx0, 1));
            mx0 = fmaxf(mx0, __shfl_xor_sync(0xffffffffu, mx0, 2));
            mx1 = fmaxf(mx1, __shfl_xor_sync(0xffffffffu, mx1, 1));
            mx1 = fmaxf(mx1, __shfl_xor_sync(0xffffffffu, mx1, 2));

            const float nm0 = fmaxf(mrow[mt][0], mx0);
            const float nm1 = fmaxf(mrow[mt][1], mx1);
            const float al0 = __expf(mrow[mt][0] - nm0);
            const float al1 = __expf(mrow[mt][1] - nm1);
            mrow[mt][0] = nm0; mrow[mt][1] = nm1;

            float ps0 = 0.f, ps1 = 0.f;
#pragma unroll
            for (int nt = 0; nt < 8; nt++) {
                s[mt][nt][0] = __expf(s[mt][nt][0] - nm0);
                s[mt][nt][1] = __expf(s[mt][nt][1] - nm0);
                s[mt][nt][2] = __expf(s[mt][nt][2] - nm1);
                s[mt][nt][3] = __expf(s[mt][nt][3] - nm1);
                ps0 += s[mt][nt][0] + s[mt][nt][1];
                ps1 += s[mt][nt][2] + s[mt][nt][3];
            }
            ps0 += __shfl_xor_sync(0xffffffffu, ps0, 1);
            ps0 += __shfl_xor_sync(0xffffffffu, ps0, 2);
            ps1 += __shfl_xor_sync(0xffffffffu, ps1, 1);
            ps1 += __shfl_xor_sync(0xffffffffu, ps1, 2);
            lrow[mt][0] = lrow[mt][0] * al0 + ps0;
            lrow[mt][1] = lrow[mt][1] * al1 + ps1;

#pragma unroll
            for (int nt = 0; nt < 8; nt++) {
                o[mt][nt][0] *= al0; o[mt][nt][1] *= al0;
                o[mt][nt][2] *= al1; o[mt][nt][3] *= al1;
            }
        }

        // ---- O += P . V  (P from registers via shuffles; V row-major) ----
#pragma unroll
        for (int ks = 0; ks < 8; ks++) {
            unsigned pa[2][4];
            p2afrag(s[0][ks], lane, tig, pa[0][0], pa[0][1], pa[0][2], pa[0][3]);
            p2afrag(s[1][ks], lane, tig, pa[1][0], pa[1][1], pa[1][2], pa[1][3]);
#pragma unroll
            for (int nt = 0; nt < 8; nt++) {
                const int vr = (ks * 8 + tig) * VLD + nt * 8 + g;
                const unsigned b0 = __float_as_uint(sV[vr]);
                const unsigned b1 = __float_as_uint(sV[vr + 4 * VLD]);
                mma_tf32(o[0][nt], pa[0][0], pa[0][1], pa[0][2], pa[0][3], b0, b1);
                mma_tf32(o[1][nt], pa[1][0], pa[1][1], pa[1][2], pa[1][3], b0, b1);
            }
        }
    }

    // ---- write out: O[q][d] / l ----
#pragma unroll
    for (int mt = 0; mt < 2; mt++) {
        const float inv0 = 1.f / lrow[mt][0];
        const float inv1 = 1.f / lrow[mt][1];
        const int row = q0 + w * 32 + mt * 16 + g;
#pragma unroll
        for (int nt = 0; nt < 8; nt++) {
            const int col = nt * 8 + 2 * tig;
            float2 v0 = make_float2(o[mt][nt][0] * inv0, o[mt][nt][1] * inv0);
            float2 v1 = make_float2(o[mt][nt][2] * inv1, o[mt][nt][3] * inv1);
            *(float2*)(O + base + (size_t)row * D_ + col)       = v0;
            *(float2*)(O + base + (size_t)(row + 8) * D_ + col) = v1;
        }
    }
}

// ---------------------------------------------------------------------------
// Launch
// ---------------------------------------------------------------------------
extern "C" void kernel_launch(void* const* d_in, const int* in_sizes, int n_in,
                              void* d_out, int out_size)
{
    const float* x  = (const float*)d_in[0];
    const float* Wq = (const float*)d_in[1];
    const float* Wk = (const float*)d_in[2];
    const float* Wv = (const float*)d_in[3];
    const float* bq = (const float*)d_in[4];
    const float* bk = (const float*)d_in[5];
    const float* bv = (const float*)d_in[6];
    const float* Wo = (const float*)d_in[7];
    const float* bo = (const float*)d_in[8];
    float* out = (float*)d_out;

    float *qp, *kp, *vp, *cp;
    cudaGetSymbolAddress((void**)&qp, g_q);
    cudaGetSymbolAddress((void**)&kp, g_k);
    cudaGetSymbolAddress((void**)&vp, g_v);
    cudaGetSymbolAddress((void**)&cp, g_c);

    cudaFuncSetAttribute(attn_tc,
                         cudaFuncAttributeMaxDynamicSharedMemorySize, ATTN_SMEM);

    const dim3 ggrid(D_ / GBN, M_TOTAL / GBM);  // (8, 64)
    const float qscale = 0.125f;                // 1/sqrt(64) folded into Q

    gemm_tc<<<ggrid, 256>>>(x, Wq, bq, qp, M_TOTAL, D_, D_, qscale);
    gemm_tc<<<ggrid, 256>>>(x, Wk, bk, kp, M_TOTAL, D_, D_, 1.0f);
    gemm_tc<<<ggrid, 256>>>(x, Wv, bv, vp, M_TOTAL, D_, D_, 1.0f);

    attn_tc<<<dim3(S_ / 128, H_, B_), 128, ATTN_SMEM>>>(qp, kp, vp, cp);

    gemm_tc<<<ggrid, 256>>>(cp, Wo, bo, out, M_TOTAL, D_, D_, 1.0f);
}

// round 5
// speedup vs baseline: 9.6409x; 1.3300x over previous
#include <cuda_runtime.h>
#include <cstdint>
#include <math.h>

// ---------------------------------------------------------------------------
// MultiHeadAttention: B=8, S=1024, D=1024, H=16, HD=64
// Round 4: mma.sync tf32 + cp.async double-buffered pipelines everywhere.
// Raw fp32 staged in smem; cvt.rna.tf32 applied at fragment-load time
// (numerically identical to converting at store time).
// Fused QKV GEMM (blockIdx.z), 64x64 warp tiles.
// ---------------------------------------------------------------------------

#define B_  8
#define S_  1024
#define D_  1024
#define H_  16
#define HD_ 64
#define M_TOTAL (B_ * S_)          // 8192

__device__ float g_q[(size_t)M_TOTAL * D_];
__device__ float g_k[(size_t)M_TOTAL * D_];
__device__ float g_v[(size_t)M_TOTAL * D_];
__device__ float g_c[(size_t)M_TOTAL * D_];

// ---------------------------------------------------------------------------
// helpers
// ---------------------------------------------------------------------------
__device__ __forceinline__ unsigned f2tf32(float f) {
    unsigned u;
    asm("cvt.rna.tf32.f32 %0, %1;" : "=r"(u) : "f"(f));
    return u;
}

__device__ __forceinline__ uint32_t smem_u32(const void* p) {
    uint32_t a;
    asm("{ .reg .u64 t; cvta.to.shared.u64 t, %1; cvt.u32.u64 %0, t; }"
        : "=r"(a) : "l"(p));
    return a;
}

__device__ __forceinline__ void cpa16(uint32_t dst, const float* src) {
    asm volatile("cp.async.cg.shared.global [%0], [%1], 16;"
                 :: "r"(dst), "l"(src) : "memory");
}
__device__ __forceinline__ void cpa_commit() {
    asm volatile("cp.async.commit_group;" ::: "memory");
}
__device__ __forceinline__ void cpa_wait1() {
    asm volatile("cp.async.wait_group 1;" ::: "memory");
}
__device__ __forceinline__ void cpa_wait0() {
    asm volatile("cp.async.wait_group 0;" ::: "memory");
}

__device__ __forceinline__ void mma_tf32(float* c,
                                         unsigned a0, unsigned a1, unsigned a2, unsigned a3,
                                         unsigned b0, unsigned b1) {
    asm volatile(
        "mma.sync.aligned.m16n8k8.row.col.f32.tf32.tf32.f32 "
        "{%0,%1,%2,%3}, {%4,%5,%6,%7}, {%8,%9}, {%0,%1,%2,%3};\n"
        : "+f"(c[0]), "+f"(c[1]), "+f"(c[2]), "+f"(c[3])
        : "r"(a0), "r"(a1), "r"(a2), "r"(a3), "r"(b0), "r"(b1));
}

// ---------------------------------------------------------------------------
// Fused tf32 GEMM: C_z[m][n] = (sum_k A[m][k]*W_z[n][k] + bias_z[n]) * scale_z
// A [8192,1024], W [1024,1024] row-major (NT gemm). CTA tile 256x128, BK=32,
// 8 warps of 64x64. cp.async double-buffered raw-fp32 smem; cvt at frag load.
// GLD=36 pad: LDS.32 frag loads conflict-free (banks (4g+tig)%32 distinct).
// ---------------------------------------------------------------------------
#define GBM 256
#define GBN 128
#define GBK 32
#define GLD 36
#define GBUF ((GBM + GBN) * GLD)                 // floats per stage buffer
#define GEMM_SMEM (2 * GBUF * 4)                 // 110592 bytes

__global__ __launch_bounds__(256, 1)
void gemm_tc(const float* __restrict__ A,
             const float* __restrict__ W0, const float* __restrict__ W1,
             const float* __restrict__ W2,
             const float* __restrict__ bb0, const float* __restrict__ bb1,
             const float* __restrict__ bb2,
             float* __restrict__ C0, float* __restrict__ C1, float* __restrict__ C2,
             float scale0)
{
    extern __shared__ float smem[];
    const int z = blockIdx.z;
    const float* Bw   = (z == 0) ? W0  : (z == 1) ? W1  : W2;
    const float* bias = (z == 0) ? bb0 : (z == 1) ? bb1 : bb2;
    float*       C    = (z == 0) ? C0  : (z == 1) ? C1  : C2;
    const float scale = (z == 0) ? scale0 : 1.0f;

    const int tid  = threadIdx.x;
    const int wid  = tid >> 5;
    const int lane = tid & 31;
    const int g    = lane >> 2;
    const int tig  = lane & 3;
    const int wm   = (wid & 3) * 64;
    const int wn   = (wid >> 2) * 64;
    const int bm   = blockIdx.y * GBM;
    const int bn   = blockIdx.x * GBN;

    const float* Abase = A  + (size_t)bm * D_;
    const float* Bbase = Bw + (size_t)bn * D_;
    const uint32_t su  = smem_u32(smem);

    // stage one BK=32 slab (A: 256x32, B: 128x32) into buffer `buf`
#define G_ISSUE(slab, buf) do {                                            \
        const uint32_t s0 = su + (uint32_t)(buf) * (GBUF * 4);             \
        const int k0 = (slab) * GBK;                                       \
        _Pragma("unroll")                                                  \
        for (int j = 0; j < 8; j++) {                                      \
            const int i = tid + 256 * j;          /* A chunks 0..2047 */   \
            const int row = i >> 3, ch = (i & 7) * 4;                      \
            cpa16(s0 + (row * GLD + ch) * 4,                               \
                  Abase + (size_t)row * D_ + k0 + ch);                     \
        }                                                                  \
        _Pragma("unroll")                                                  \
        for (int j = 0; j < 4; j++) {                                      \
            const int i = tid + 256 * j;          /* B chunks 0..1023 */   \
            const int row = i >> 3, ch = (i & 7) * 4;                      \
            cpa16(s0 + ((GBM + row) * GLD + ch) * 4,                       \
                  Bbase + (size_t)row * D_ + k0 + ch);                     \
        }                                                                  \
        cpa_commit();                                                      \
    } while (0)

    float acc[4][8][4];
#pragma unroll
    for (int mt = 0; mt < 4; mt++)
#pragma unroll
        for (int nt = 0; nt < 8; nt++)
#pragma unroll
            for (int i = 0; i < 4; i++) acc[mt][nt][i] = 0.f;

    const int NT = D_ / GBK;   // 32
    G_ISSUE(0, 0);
    G_ISSUE(1, 1);

    for (int t = 0; t < NT; t++) {
        if (t == NT - 1) cpa_wait0(); else cpa_wait1();
        __syncthreads();

        const float* as = smem + (t & 1) * GBUF;
        const float* bs = as + GBM * GLD;
#pragma unroll
        for (int ks = 0; ks < 4; ks++) {
            unsigned af[4][4];
#pragma unroll
            for (int mt = 0; mt < 4; mt++) {
                const int qr = (wm + mt * 16 + g) * GLD + ks * 8;
                af[mt][0] = f2tf32(as[qr + tig]);
                af[mt][1] = f2tf32(as[qr + 8 * GLD + tig]);
                af[mt][2] = f2tf32(as[qr + tig + 4]);
                af[mt][3] = f2tf32(as[qr + 8 * GLD + tig + 4]);
            }
#pragma unroll
            for (int nt = 0; nt < 8; nt++) {
                const int kr = (wn + nt * 8 + g) * GLD + ks * 8;
                const unsigned b0 = f2tf32(bs[kr + tig]);
                const unsigned b1 = f2tf32(bs[kr + tig + 4]);
#pragma unroll
                for (int mt = 0; mt < 4; mt++)
                    mma_tf32(acc[mt][nt], af[mt][0], af[mt][1], af[mt][2], af[mt][3],
                             b0, b1);
            }
        }
        __syncthreads();
        if (t + 2 < NT) G_ISSUE(t + 2, t & 1);
    }
#undef G_ISSUE

    // epilogue
#pragma unroll
    for (int mt = 0; mt < 4; mt++) {
        const int row0 = bm + wm + mt * 16 + g;
#pragma unroll
        for (int nt = 0; nt < 8; nt++) {
            const int col = bn + wn + nt * 8 + 2 * tig;
            const float c0 = bias[col], c1 = bias[col + 1];
            float2 v0 = make_float2((acc[mt][nt][0] + c0) * scale,
                                    (acc[mt][nt][1] + c1) * scale);
            float2 v1 = make_float2((acc[mt][nt][2] + c0) * scale,
                                    (acc[mt][nt][3] + c1) * scale);
            *(float2*)(C + (size_t)row0 * D_ + col)       = v0;
            *(float2*)(C + (size_t)(row0 + 8) * D_ + col) = v1;
        }
    }
}

// ---------------------------------------------------------------------------
// Flash attention, tf32 mma.sync, cp.async double-buffered K/V.
// CTA = (b, h, 128-row q-tile), 4 warps x 32 q-rows (2 m-tiles each).
// Raw fp32 in smem, cvt at frag load. Pads: QLD/KLD 68, VLD 72 (conflict-free).
// P stays in registers (quad-shuffle S->A-fragment conversion).
// ---------------------------------------------------------------------------
#define QLD 68
#define KLD 68
#define VLD 72
// sQ | sK0 sK1 | sV0 sV1
#define OFF_K(buf) (128 * QLD + (buf) * 64 * KLD)
#define OFF_V(buf) (128 * QLD + 2 * 64 * KLD + (buf) * 64 * VLD)
#define ATTN_SMEM ((128 * QLD + 2 * 64 * KLD + 2 * 64 * VLD) * 4)   // 106496 B

__device__ __forceinline__ void p2afrag(const float sv[4], int lane, int tig,
                                        unsigned& a0, unsigned& a1,
                                        unsigned& a2, unsigned& a3) {
    const unsigned F = 0xffffffffu;
    const int s0l = (lane & ~3) | (tig >> 1);
    const int s1l = s0l + 2;
    float v00 = __shfl_sync(F, sv[0], s0l);
    float v01 = __shfl_sync(F, sv[1], s0l);
    float v10 = __shfl_sync(F, sv[0], s1l);
    float v11 = __shfl_sync(F, sv[1], s1l);
    float w00 = __shfl_sync(F, sv[2], s0l);
    float w01 = __shfl_sync(F, sv[3], s0l);
    float w10 = __shfl_sync(F, sv[2], s1l);
    float w11 = __shfl_sync(F, sv[3], s1l);
    const bool odd = (tig & 1);
    a0 = f2tf32(odd ? v01 : v00);
    a2 = f2tf32(odd ? v11 : v10);
    a1 = f2tf32(odd ? w01 : w00);
    a3 = f2tf32(odd ? w11 : w10);
}

__global__ __launch_bounds__(128)
void attn_tc(const float* __restrict__ Q, const float* __restrict__ K,
             const float* __restrict__ V, float* __restrict__ O)
{
    extern __shared__ float sm[];
    const uint32_t su = smem_u32(sm);

    const int q0   = blockIdx.x * 128;
    const int h    = blockIdx.y;
    const int b    = blockIdx.z;
    const int tid  = threadIdx.x;
    const int w    = tid >> 5;
    const int lane = tid & 31;
    const int g    = lane >> 2;
    const int tig  = lane & 3;

    const size_t base = (size_t)b * S_ * D_ + (size_t)h * HD_;

    // issue K/V tile `t` into buffer `buf` (64 rows x 64 floats each)
#define A_ISSUE(t, buf) do {                                               \
        const float* Kb = K + base + (size_t)((t) * 64) * D_;              \
        const float* Vb = V + base + (size_t)((t) * 64) * D_;              \
        _Pragma("unroll")                                                  \
        for (int j = 0; j < 8; j++) {                                      \
            const int i = tid + 128 * j;                                   \
            const int row = i >> 4, c4 = (i & 15) * 4;                     \
            cpa16(su + (OFF_K(buf) + row * KLD + c4) * 4,                  \
                  Kb + (size_t)row * D_ + c4);                             \
            cpa16(su + (OFF_V(buf) + row * VLD + c4) * 4,                  \
                  Vb + (size_t)row * D_ + c4);                             \
        }                                                                  \
        cpa_commit();                                                      \
    } while (0)

    // prologue: group0 = Q tile + K/V tile 0; group1 = K/V tile 1
    {
        const float* Qb = Q + base + (size_t)q0 * D_;
        const float* Kb = K + base;
        const float* Vb = V + base;
#pragma unroll
        for (int j = 0; j < 16; j++) {
            const int i = tid + 128 * j;
            const int row = i >> 4, c4 = (i & 15) * 4;
            cpa16(su + (row * QLD + c4) * 4, Qb + (size_t)row * D_ + c4);
        }
#pragma unroll
        for (int j = 0; j < 8; j++) {
            const int i = tid + 128 * j;
            const int row = i >> 4, c4 = (i & 15) * 4;
            cpa16(su + (OFF_K(0) + row * KLD + c4) * 4, Kb + (size_t)row * D_ + c4);
            cpa16(su + (OFF_V(0) + row * VLD + c4) * 4, Vb + (size_t)row * D_ + c4);
        }
        cpa_commit();
        A_ISSUE(1, 1);
    }

    float mrow[2][2], lrow[2][2];
#pragma unroll
    for (int mt = 0; mt < 2; mt++) {
        mrow[mt][0] = -1e30f; mrow[mt][1] = -1e30f;
        lrow[mt][0] = 0.f;    lrow[mt][1] = 0.f;
    }
    float o[2][8][4];
#pragma unroll
    for (int mt = 0; mt < 2; mt++)
#pragma unroll
        for (int nt = 0; nt < 8; nt++)
#pragma unroll
            for (int i = 0; i < 4; i++) o[mt][nt][i] = 0.f;

    const int NTILE = S_ / 64;   // 16
    for (int t = 0; t < NTILE; t++) {
        if (t == NTILE - 1) cpa_wait0(); else cpa_wait1();
        __syncthreads();

        const float* sQ = sm;
        const float* sK = sm + OFF_K(t & 1);
        const float* sV = sm + OFF_V(t & 1);

        // ---- S = Q . K^T : 2 m-tiles x 64 keys per warp ----
        float s[2][8][4];
#pragma unroll
        for (int mt = 0; mt < 2; mt++)
#pragma unroll
            for (int nt = 0; nt < 8; nt++)
#pragma unroll
                for (int i = 0; i < 4; i++) s[mt][nt][i] = 0.f;

#pragma unroll
        for (int ks = 0; ks < 8; ks++) {
            unsigned af[2][4];
#pragma unroll
            for (int mt = 0; mt < 2; mt++) {
                const int qr = (w * 32 + mt * 16 + g) * QLD + ks * 8;
                af[mt][0] = f2tf32(sQ[qr + tig]);
                af[mt][1] = f2tf32(sQ[qr + 8 * QLD + tig]);
                af[mt][2] = f2tf32(sQ[qr + tig + 4]);
                af[mt][3] = f2tf32(sQ[qr + 8 * QLD + tig + 4]);
            }
#pragma unroll
            for (int nt = 0; nt < 8; nt++) {
                const int kr = (nt * 8 + g) * KLD + ks * 8;
                const unsigned b0 = f2tf32(sK[kr + tig]);
                const unsigned b1 = f2tf32(sK[kr + tig + 4]);
                mma_tf32(s[0][nt], af[0][0], af[0][1], af[0][2], af[0][3], b0, b1);
                mma_tf32(s[1][nt], af[1][0], af[1][1], af[1][2], af[1][3], b0, b1);
            }
        }

        // ---- online softmax per m-tile; s becomes P (fp32) in place ----
#pragma unroll
        for (int mt = 0; mt < 2; mt++) {
            float mx0 = -1e30f, mx1 = -1e30f;
#pragma unroll
            for (int nt = 0; nt < 8; nt++) {
                mx0 = fmaxf(mx0, fmaxf(s[mt][nt][0], s[mt][nt][1]));
                mx1 = fmaxf(mx1, fmaxf(s[mt][nt][2], s[mt][nt][3]));
            }
            mx0 = fmaxf(mx0, __shfl_xor_sync(0xffffffffu, mx0, 1));
            mx0 = fmaxf(mx0, __shfl_xor_sync(0xffffffffu, mx0, 2));
            mx1 = fmaxf(mx1, __shfl_xor_sync(0xffffffffu, mx1, 1));
            mx1 = fmaxf(mx1, __shfl_xor_sync(0xffffffffu, mx1, 2));

            const float nm0 = fmaxf(mrow[mt][0], mx0);
            const float nm1 = fmaxf(mrow[mt][1], mx1);
            const float al0 = __expf(mrow[mt][0] - nm0);
            const float al1 = __expf(mrow[mt][1] - nm1);
            mrow[mt][0] = nm0; mrow[mt][1] = nm1;

            float ps0 = 0.f, ps1 = 0.f;
#pragma unroll
            for (int nt = 0; nt < 8; nt++) {
                s[mt][nt][0] = __expf(s[mt][nt][0] - nm0);
                s[mt][nt][1] = __expf(s[mt][nt][1] - nm0);
                s[mt][nt][2] = __expf(s[mt][nt][2] - nm1);
                s[mt][nt][3] = __expf(s[mt][nt][3] - nm1);
                ps0 += s[mt][nt][0] + s[mt][nt][1];
                ps1 += s[mt][nt][2] + s[mt][nt][3];
            }
            ps0 += __shfl_xor_sync(0xffffffffu, ps0, 1);
            ps0 += __shfl_xor_sync(0xffffffffu, ps0, 2);
            ps1 += __shfl_xor_sync(0xffffffffu, ps1, 1);
            ps1 += __shfl_xor_sync(0xffffffffu, ps1, 2);
            lrow[mt][0] = lrow[mt][0] * al0 + ps0;
            lrow[mt][1] = lrow[mt][1] * al1 + ps1;

#pragma unroll
            for (int nt = 0; nt < 8; nt++) {
                o[mt][nt][0] *= al0; o[mt][nt][1] *= al0;
                o[mt][nt][2] *= al1; o[mt][nt][3] *= al1;
            }
        }

        // ---- O += P . V  (P from registers; V row-major) ----
#pragma unroll
        for (int ks = 0; ks < 8; ks++) {
            unsigned pa[2][4];
            p2afrag(s[0][ks], lane, tig, pa[0][0], pa[0][1], pa[0][2], pa[0][3]);
            p2afrag(s[1][ks], lane, tig, pa[1][0], pa[1][1], pa[1][2], pa[1][3]);
#pragma unroll
            for (int nt = 0; nt < 8; nt++) {
                const int vr = (ks * 8 + tig) * VLD + nt * 8 + g;
                const unsigned b0 = f2tf32(sV[vr]);
                const unsigned b1 = f2tf32(sV[vr + 4 * VLD]);
                mma_tf32(o[0][nt], pa[0][0], pa[0][1], pa[0][2], pa[0][3], b0, b1);
                mma_tf32(o[1][nt], pa[1][0], pa[1][1], pa[1][2], pa[1][3], b0, b1);
            }
        }

        __syncthreads();
        if (t + 2 < NTILE) A_ISSUE(t + 2, t & 1);
    }
#undef A_ISSUE

    // ---- write out: O[q][d] / l ----
#pragma unroll
    for (int mt = 0; mt < 2; mt++) {
        const float inv0 = 1.f / lrow[mt][0];
        const float inv1 = 1.f / lrow[mt][1];
        const int row = q0 + w * 32 + mt * 16 + g;
#pragma unroll
        for (int nt = 0; nt < 8; nt++) {
            const int col = nt * 8 + 2 * tig;
            float2 v0 = make_float2(o[mt][nt][0] * inv0, o[mt][nt][1] * inv0);
            float2 v1 = make_float2(o[mt][nt][2] * inv1, o[mt][nt][3] * inv1);
            *(float2*)(O + base + (size_t)row * D_ + col)       = v0;
            *(float2*)(O + base + (size_t)(row + 8) * D_ + col) = v1;
        }
    }
}

// ---------------------------------------------------------------------------
// Launch
// ---------------------------------------------------------------------------
extern "C" void kernel_launch(void* const* d_in, const int* in_sizes, int n_in,
                              void* d_out, int out_size)
{
    const float* x  = (const float*)d_in[0];
    const float* Wq = (const float*)d_in[1];
    const float* Wk = (const float*)d_in[2];
    const float* Wv = (const float*)d_in[3];
    const float* bq = (const float*)d_in[4];
    const float* bk = (const float*)d_in[5];
    const float* bv = (const float*)d_in[6];
    const float* Wo = (const float*)d_in[7];
    const float* bo = (const float*)d_in[8];
    float* out = (float*)d_out;

    float *qp, *kp, *vp, *cp;
    cudaGetSymbolAddress((void**)&qp, g_q);
    cudaGetSymbolAddress((void**)&kp, g_k);
    cudaGetSymbolAddress((void**)&vp, g_v);
    cudaGetSymbolAddress((void**)&cp, g_c);

    cudaFuncSetAttribute(gemm_tc,
                         cudaFuncAttributeMaxDynamicSharedMemorySize, GEMM_SMEM);
    cudaFuncSetAttribute(attn_tc,
                         cudaFuncAttributeMaxDynamicSharedMemorySize, ATTN_SMEM);

    // fused QKV: grid z selects (Wq,bq,q*0.125) / (Wk,bk,k) / (Wv,bv,v)
    gemm_tc<<<dim3(D_ / GBN, M_TOTAL / GBM, 3), 256, GEMM_SMEM>>>(
        x, Wq, Wk, Wv, bq, bk, bv, qp, kp, vp, 0.125f);

    attn_tc<<<dim3(S_ / 128, H_, B_), 128, ATTN_SMEM>>>(qp, kp, vp, cp);

    // output projection: z-extent 1 -> slot 0, scale 1
    gemm_tc<<<dim3(D_ / GBN, M_TOTAL / GBM, 1), 256, GEMM_SMEM>>>(
        cp, Wo, Wo, Wo, bo, bo, bo, out, out, out, 1.0f);
}